// round 1
// baseline (speedup 1.0000x reference)
#include <cuda_runtime.h>
#include <cuda_bf16.h>
#include <cstdint>

#define BATCH 2048
#define DDIM  128
#define MDIM  256
#define NKEYS 32768
#define NTILES (NKEYS / 128)   // 256 column tiles
#define EST_CONST 0.0048957583f  // float32(sqrt(pi/2)/256)

// -------- static device scratch (no allocations allowed) --------
__device__ __nv_bfloat16 g_Ahi[BATCH * MDIM];
__device__ __nv_bfloat16 g_Alo[BATCH * MDIM];
__device__ float  g_part[(size_t)BATCH * NTILES * 2];  // (max, sumexp) per (row, ctile)
__device__ float2 g_rowstats[BATCH];                   // (M, 1/S)

// ---------------------------------------------------------------
// K1: PQ = query @ sketch^T (fp32), split into bf16 hi/lo
// grid 2048 (one per batch row), 256 threads (one per m)
// ---------------------------------------------------------------
__global__ void project_kernel(const float* __restrict__ query,
                               const float* __restrict__ sketch) {
    __shared__ float4 qs[DDIM / 4];
    int b = blockIdx.x;
    if (threadIdx.x < DDIM / 4)
        qs[threadIdx.x] = ((const float4*)(query + (size_t)b * DDIM))[threadIdx.x];
    __syncthreads();

    int m = threadIdx.x;  // 0..255
    const float4* skr = (const float4*)(sketch + (size_t)m * DDIM);
    float acc = 0.f;
#pragma unroll
    for (int i = 0; i < DDIM / 4; i++) {
        float4 a = qs[i];
        float4 s = skr[i];
        acc += a.x * s.x + a.y * s.y + a.z * s.z + a.w * s.w;
    }
    __nv_bfloat16 hi = __float2bfloat16(acc);
    float rem = acc - __bfloat162float(hi);
    __nv_bfloat16 lo = __float2bfloat16(rem);
    g_Ahi[(size_t)b * MDIM + m] = hi;
    g_Alo[(size_t)b * MDIM + m] = lo;
}

// ---------------------------------------------------------------
// K2: scores = EST * norms[n] * (Ahi+Alo) @ keys^T  (bf16 mma, fp32 acc)
// CTA tile 128x128, K=256 in 8 chunks of 32, hi+lo passes.
// Writes raw scores to out, plus per-(row, ctile) (max, sumexp) partials.
// grid = (16 row slabs, 256 col tiles); m-fastest for key-tile L2 sharing.
// ---------------------------------------------------------------
__device__ __forceinline__ void mma16816(float* c, const unsigned* a, const unsigned* b) {
    asm volatile(
        "mma.sync.aligned.m16n8k16.row.col.f32.bf16.bf16.f32 "
        "{%0,%1,%2,%3}, {%4,%5,%6,%7}, {%8,%9}, {%0,%1,%2,%3};\n"
        : "+f"(c[0]), "+f"(c[1]), "+f"(c[2]), "+f"(c[3])
        : "r"(a[0]), "r"(a[1]), "r"(a[2]), "r"(a[3]), "r"(b[0]), "r"(b[1]));
}

#define SSTR 20  // smem row stride in 32-bit words (40 bf16) — conflict-free

__global__ __launch_bounds__(256, 2)
void gemm_kernel(const float* __restrict__ keys,
                 const float* __restrict__ norms,
                 float* __restrict__ out) {
    __shared__ __align__(16) unsigned sAhi[128 * SSTR];
    __shared__ __align__(16) unsigned sAlo[128 * SSTR];
    __shared__ __align__(16) unsigned sS[128 * SSTR];
    __shared__ float sNorm[128];
    __shared__ float sRed[2][128][2];

    const int row0 = blockIdx.x * 128;
    const int n0   = blockIdx.y * 128;
    const int tid  = threadIdx.x;
    const int wid  = tid >> 5;
    const int lane = tid & 31;
    const int warp_m = wid & 3;   // 4 warps over 128 rows (32 each)
    const int warp_n = wid >> 2;  // 2 warps over 128 cols (64 each)
    const int g = lane >> 2;      // group 0..7
    const int q = lane & 3;       // quad  0..3

    if (tid < 128) sNorm[tid] = __ldg(norms + n0 + tid);

    float acc[2][8][4];
#pragma unroll
    for (int mt = 0; mt < 2; mt++)
#pragma unroll
        for (int nt = 0; nt < 8; nt++)
#pragma unroll
            for (int c = 0; c < 4; c++) acc[mt][nt][c] = 0.f;

    const unsigned* gAhi = reinterpret_cast<const unsigned*>(g_Ahi);
    const unsigned* gAlo = reinterpret_cast<const unsigned*>(g_Alo);

    for (int kc = 0; kc < 8; kc++) {
        if (kc) __syncthreads();
        // --- load A hi/lo: 128 rows x 16 words each ---
        {
            int r = tid >> 4;        // 0..15
            int c = tid & 15;        // word 0..15
#pragma unroll
            for (int rr = 0; rr < 128; rr += 16) {
                size_t gidx = (size_t)(row0 + r + rr) * (MDIM / 2) + kc * 16 + c;
                sAhi[(r + rr) * SSTR + c] = gAhi[gidx];
                sAlo[(r + rr) * SSTR + c] = gAlo[gidx];
            }
        }
        // --- load key tile 128x32 fp32 -> bf16 ---
        {
            int r  = tid >> 1;        // 0..127
            int c0 = (tid & 1) * 16;  // float offset
            const float4* kp = (const float4*)(keys + (size_t)(n0 + r) * MDIM + kc * 32 + c0);
#pragma unroll
            for (int j = 0; j < 4; j++) {
                float4 v = __ldg(kp + j);
                __nv_bfloat162 w0 = __floats2bfloat162_rn(v.x, v.y);
                __nv_bfloat162 w1 = __floats2bfloat162_rn(v.z, v.w);
                int wcol = c0 / 2 + j * 2;
                sS[r * SSTR + wcol]     = *reinterpret_cast<unsigned*>(&w0);
                sS[r * SSTR + wcol + 1] = *reinterpret_cast<unsigned*>(&w1);
            }
        }
        __syncthreads();

#pragma unroll
        for (int pass = 0; pass < 2; pass++) {
            const unsigned* sA = pass ? sAlo : sAhi;
#pragma unroll
            for (int kk = 0; kk < 2; kk++) {
                const int kw = kk * 8 + q;
                unsigned afrag[2][4], bfrag[8][2];
#pragma unroll
                for (int mt = 0; mt < 2; mt++) {
                    int mrow = warp_m * 32 + mt * 16;
                    afrag[mt][0] = sA[(mrow + g) * SSTR + kw];
                    afrag[mt][1] = sA[(mrow + g + 8) * SSTR + kw];
                    afrag[mt][2] = sA[(mrow + g) * SSTR + kw + 4];
                    afrag[mt][3] = sA[(mrow + g + 8) * SSTR + kw + 4];
                }
#pragma unroll
                for (int nt = 0; nt < 8; nt++) {
                    int ncol = warp_n * 64 + nt * 8 + g;
                    bfrag[nt][0] = sS[ncol * SSTR + kw];
                    bfrag[nt][1] = sS[ncol * SSTR + kw + 4];
                }
#pragma unroll
                for (int mt = 0; mt < 2; mt++)
#pragma unroll
                    for (int nt = 0; nt < 8; nt++)
                        mma16816(acc[mt][nt], afrag[mt], bfrag[nt]);
            }
        }
    }

    // ---- epilogue: scale into scores (in place), write out ----
#pragma unroll
    for (int mt = 0; mt < 2; mt++) {
#pragma unroll
        for (int nt = 0; nt < 8; nt++) {
            int cl = warp_n * 64 + nt * 8 + 2 * q;
            float s0 = EST_CONST * sNorm[cl];
            float s1 = EST_CONST * sNorm[cl + 1];
            acc[mt][nt][0] *= s0;
            acc[mt][nt][1] *= s1;
            acc[mt][nt][2] *= s0;
            acc[mt][nt][3] *= s1;
        }
        // two row-halves per mma tile
#pragma unroll
        for (int h = 0; h < 2; h++) {
            int rloc = warp_m * 32 + mt * 16 + g + h * 8;
            size_t orow = (size_t)(row0 + rloc) * NKEYS + n0;
            float mymax = -3.0e38f;
#pragma unroll
            for (int nt = 0; nt < 8; nt++) {
                int cl = warp_n * 64 + nt * 8 + 2 * q;
                float v0 = acc[mt][nt][h * 2 + 0];
                float v1 = acc[mt][nt][h * 2 + 1];
                float2 o = make_float2(v0, v1);
                *reinterpret_cast<float2*>(out + orow + cl) = o;
                mymax = fmaxf(mymax, fmaxf(v0, v1));
            }
            float s = 0.f;
#pragma unroll
            for (int nt = 0; nt < 8; nt++) {
                s += __expf(acc[mt][nt][h * 2 + 0] - mymax);
                s += __expf(acc[mt][nt][h * 2 + 1] - mymax);
            }
            // quad (lanes differing in q) log-sum-exp reduce
#pragma unroll
            for (int off = 1; off <= 2; off <<= 1) {
                float mo = __shfl_xor_sync(0xffffffffu, mymax, off);
                float so = __shfl_xor_sync(0xffffffffu, s, off);
                float nm = fmaxf(mymax, mo);
                s = s * __expf(mymax - nm) + so * __expf(mo - nm);
                mymax = nm;
            }
            if (q == 0) {
                sRed[warp_n][rloc][0] = mymax;
                sRed[warp_n][rloc][1] = s;
            }
        }
    }
    __syncthreads();
    if (tid < 128) {
        float m0 = sRed[0][tid][0], s0 = sRed[0][tid][1];
        float m1 = sRed[1][tid][0], s1 = sRed[1][tid][1];
        float M = fmaxf(m0, m1);
        float S = s0 * __expf(m0 - M) + s1 * __expf(m1 - M);
        size_t pidx = ((size_t)(row0 + tid) * NTILES + blockIdx.y) * 2;
        g_part[pidx]     = M;
        g_part[pidx + 1] = S;
    }
}

// ---------------------------------------------------------------
// K3: per-row log-sum-exp reduction of 256 partials
// grid 2048, 256 threads
// ---------------------------------------------------------------
__global__ void reduce_kernel() {
    int b = blockIdx.x, t = threadIdx.x;
    size_t base = ((size_t)b * NTILES + t) * 2;
    float m = g_part[base];
    float s = g_part[base + 1];
#pragma unroll
    for (int off = 16; off; off >>= 1) {
        float mo = __shfl_xor_sync(0xffffffffu, m, off);
        float so = __shfl_xor_sync(0xffffffffu, s, off);
        float nm = fmaxf(m, mo);
        s = s * __expf(m - nm) + so * __expf(mo - nm);
        m = nm;
    }
    __shared__ float sm[8], ss[8];
    if ((t & 31) == 0) { sm[t >> 5] = m; ss[t >> 5] = s; }
    __syncthreads();
    if (t < 32) {
        if (t < 8) { m = sm[t]; s = ss[t]; }
        else       { m = -3.0e38f; s = 0.f; }
#pragma unroll
        for (int off = 4; off; off >>= 1) {
            float mo = __shfl_xor_sync(0xffffffffu, m, off);
            float so = __shfl_xor_sync(0xffffffffu, s, off);
            float nm = fmaxf(m, mo);
            s = s * __expf(m - nm) + so * __expf(mo - nm);
            m = nm;
        }
        if (t == 0) g_rowstats[b] = make_float2(m, 1.0f / s);
    }
}

// ---------------------------------------------------------------
// K4: out = exp(score - M) * invS   (in-place over d_out)
// ---------------------------------------------------------------
__global__ void norm_kernel(float* __restrict__ out) {
    const size_t total4 = (size_t)BATCH * NKEYS / 4;
    size_t stride = (size_t)gridDim.x * blockDim.x;
    for (size_t i4 = (size_t)blockIdx.x * blockDim.x + threadIdx.x;
         i4 < total4; i4 += stride) {
        int b = (int)(i4 >> 13);  // 32768/4 = 8192 float4 per row
        float2 st = __ldg(&g_rowstats[b]);
        float4 v = reinterpret_cast<float4*>(out)[i4];
        v.x = __expf(v.x - st.x) * st.y;
        v.y = __expf(v.y - st.x) * st.y;
        v.z = __expf(v.z - st.x) * st.y;
        v.w = __expf(v.w - st.x) * st.y;
        reinterpret_cast<float4*>(out)[i4] = v;
    }
}

// ---------------------------------------------------------------
extern "C" void kernel_launch(void* const* d_in, const int* in_sizes, int n_in,
                              void* d_out, int out_size) {
    const float* query  = (const float*)d_in[0];  // [2048, 128]
    const float* keys   = (const float*)d_in[1];  // [32768, 256] (+/-1)
    const float* norms  = (const float*)d_in[2];  // [32768]
    const float* sketch = (const float*)d_in[3];  // [256, 128]
    float* out = (float*)d_out;                   // [2048, 32768]

    project_kernel<<<BATCH, 256>>>(query, sketch);
    dim3 g2(BATCH / 128, NTILES);  // m-fastest: 16 slabs share each key tile in-wave
    gemm_kernel<<<g2, 256>>>(keys, norms, out);
    reduce_kernel<<<BATCH, 256>>>();
    norm_kernel<<<16384, 256>>>(out);
}

// round 4
// speedup vs baseline: 1.1859x; 1.1859x over previous
#include <cuda_runtime.h>
#include <cuda_bf16.h>
#include <cstdint>

#define BATCH 2048
#define DDIM  128
#define MDIM  256
#define NKEYS 32768
#define NTILE 256                  // keys per CTA tile
#define CTILES (NKEYS / NTILE)     // 128
#define EST_CONST 0.0048957583f    // float32(sqrt(pi/2)/256)

// -------- static device scratch (no allocations allowed) --------
__device__ __align__(16) __nv_bfloat16 g_Ahi[BATCH * MDIM];
__device__ __align__(16) __nv_bfloat16 g_Alo[BATCH * MDIM];
__device__ __align__(16) __nv_bfloat16 g_Kbf[(size_t)NKEYS * MDIM];
__device__ float  g_part[(size_t)BATCH * CTILES * 2];
__device__ float2 g_rowstats[BATCH];

// ---------------- PTX helpers (compute_103-safe: no tcgen05) ----------------
__device__ __forceinline__ uint32_t smem_u32(const void* p) {
    uint32_t a;
    asm("{ .reg .u64 t; cvta.to.shared.u64 t, %1; cvt.u32.u64 %0, t; }" : "=r"(a) : "l"(p));
    return a;
}
__device__ __forceinline__ void cpa16(uint32_t dst, const void* src) {
    asm volatile("cp.async.cg.shared.global [%0], [%1], 16;" :: "r"(dst), "l"(src));
}
#define CP_COMMIT() asm volatile("cp.async.commit_group;" ::: "memory")
template <int N> __device__ __forceinline__ void cp_wait() {
    asm volatile("cp.async.wait_group %0;" :: "n"(N) : "memory");
}
__device__ __forceinline__ void ldm_x4(unsigned* r, uint32_t addr) {
    asm volatile("ldmatrix.sync.aligned.m8n8.x4.shared.b16 {%0,%1,%2,%3}, [%4];"
                 : "=r"(r[0]), "=r"(r[1]), "=r"(r[2]), "=r"(r[3]) : "r"(addr));
}
__device__ __forceinline__ void mma16816(float* c, const unsigned* a, const unsigned* b) {
    asm volatile(
        "mma.sync.aligned.m16n8k16.row.col.f32.bf16.bf16.f32 "
        "{%0,%1,%2,%3}, {%4,%5,%6,%7}, {%8,%9}, {%0,%1,%2,%3};\n"
        : "+f"(c[0]), "+f"(c[1]), "+f"(c[2]), "+f"(c[3])
        : "r"(a[0]), "r"(a[1]), "r"(a[2]), "r"(a[3]), "r"(b[0]), "r"(b[1]));
}

// ---------------------------------------------------------------
// K0: convert keys fp32 -> bf16 (keys are +/-1: exact)
// ---------------------------------------------------------------
__global__ void convert_keys(const float* __restrict__ keys) {
    size_t i = (size_t)blockIdx.x * blockDim.x + threadIdx.x;  // one float4 each
    float4 v = __ldg((const float4*)keys + i);
    __nv_bfloat162 a = __floats2bfloat162_rn(v.x, v.y);
    __nv_bfloat162 b = __floats2bfloat162_rn(v.z, v.w);
    ((__nv_bfloat162*)g_Kbf)[2 * i]     = a;
    ((__nv_bfloat162*)g_Kbf)[2 * i + 1] = b;
}

// ---------------------------------------------------------------
// K1: PQ = query @ sketch^T (fp32), split into bf16 hi/lo
// ---------------------------------------------------------------
__global__ void project_kernel(const float* __restrict__ query,
                               const float* __restrict__ sketch) {
    __shared__ float4 qs[DDIM / 4];
    int b = blockIdx.x;
    if (threadIdx.x < DDIM / 4)
        qs[threadIdx.x] = ((const float4*)(query + (size_t)b * DDIM))[threadIdx.x];
    __syncthreads();

    int m = threadIdx.x;  // 0..255
    const float4* skr = (const float4*)(sketch + (size_t)m * DDIM);
    float acc = 0.f;
#pragma unroll
    for (int i = 0; i < DDIM / 4; i++) {
        float4 a = qs[i];
        float4 s = skr[i];
        acc += a.x * s.x + a.y * s.y + a.z * s.z + a.w * s.w;
    }
    __nv_bfloat16 hi = __float2bfloat16(acc);
    float rem = acc - __bfloat162float(hi);
    g_Ahi[(size_t)b * MDIM + m] = hi;
    g_Alo[(size_t)b * MDIM + m] = __float2bfloat16(rem);
}

// ---------------------------------------------------------------
// K2: HMMA GEMM. CTA tile 128(M) x 256(N), K=256 in 8 chunks of 32.
// hi/lo folded per chunk into one fp32 acc. cp.async double buffer.
// 8 warps, warp tile 64x64 (warp_m = wid&1, warp_n = wid>>1).
// Rows padded to 80B -> ldmatrix conflict-free.
// ---------------------------------------------------------------
#define ROWB 80                      // bytes per smem row (32 bf16 + pad)
#define ASZ  (128 * ROWB)            // 10240 B per A operand
#define BSZ  (256 * ROWB)            // 20480 B
#define STAGE (2 * ASZ + BSZ)        // 40960 B
#define SMEM_DYN (2 * STAGE)         // 81920 B

__global__ void __launch_bounds__(256, 1)
gemm_kernel(const float* __restrict__ norms, float* __restrict__ out) {
    extern __shared__ char dsm[];
    __shared__ float  sNorm[NTILE];
    __shared__ float2 sRed[4][128];

    const int tid  = threadIdx.x;
    const int wid  = tid >> 5;
    const int lane = tid & 31;
    const int warp_m = wid & 1;   // 2 over 128 rows (64 each)
    const int warp_n = wid >> 1;  // 4 over 256 cols (64 each)
    const int g = lane >> 2;
    const int q = lane & 3;
    const int row0 = blockIdx.x * 128;
    const int n0   = blockIdx.y * NTILE;

    const uint32_t base = smem_u32(dsm);

    for (int i = tid; i < NTILE; i += 256)
        sNorm[i] = __ldg(norms + n0 + i) * EST_CONST;

    float acc[4][8][4];
#pragma unroll
    for (int mt = 0; mt < 4; mt++)
#pragma unroll
        for (int nt = 0; nt < 8; nt++)
#pragma unroll
            for (int c = 0; c < 4; c++) acc[mt][nt][c] = 0.f;

    // per-lane ldmatrix address components
    const int aRow = warp_m * 64 + (lane & 7) + ((lane >> 3) & 1) * 8;  // + mt*16
    const int aKh  = (lane >> 4) * 16;                                   // k-half bytes
    const int bRow = warp_n * 64 + (lane & 7) + ((lane >> 4) & 1) * 8;  // + ntp*16
    const int bKh  = ((lane >> 3) & 1) * 16;

    auto load_chunk = [&](int kc, int buf) {
        const uint32_t sb = base + buf * STAGE;
        const __nv_bfloat16* srcH = g_Ahi + (size_t)row0 * MDIM + kc * 32;
        const __nv_bfloat16* srcL = g_Alo + (size_t)row0 * MDIM + kc * 32;
        const __nv_bfloat16* srcB = g_Kbf + (size_t)n0 * MDIM + kc * 32;
#pragma unroll
        for (int i = 0; i < 2; i++) {            // A hi/lo: 128 rows x 4 segs
            int idx = tid + i * 256;
            int r = idx >> 2, sg = idx & 3;
            uint32_t so = (uint32_t)(r * ROWB + sg * 16);
            cpa16(sb + so,       srcH + (size_t)r * MDIM + sg * 8);
            cpa16(sb + ASZ + so, srcL + (size_t)r * MDIM + sg * 8);
        }
#pragma unroll
        for (int i = 0; i < 4; i++) {            // B: 256 rows x 4 segs
            int idx = tid + i * 256;
            int r = idx >> 2, sg = idx & 3;
            cpa16(sb + 2 * ASZ + (uint32_t)(r * ROWB + sg * 16),
                  srcB + (size_t)r * MDIM + sg * 8);
        }
        CP_COMMIT();
    };

    auto compute = [&](int buf) {
        const uint32_t sb  = base + buf * STAGE;
        const uint32_t aH  = sb;
        const uint32_t aL  = sb + ASZ;
        const uint32_t bB  = sb + 2 * ASZ;
#pragma unroll
        for (int kk = 0; kk < 2; kk++) {
            const int kb = kk * 32;  // 16 bf16 = 32 bytes
            unsigned ah[4][4], al[4][4], bb[8][2];
#pragma unroll
            for (int mt = 0; mt < 4; mt++) {
                uint32_t ao = (uint32_t)((aRow + mt * 16) * ROWB + kb + aKh);
                ldm_x4(ah[mt], aH + ao);
                ldm_x4(al[mt], aL + ao);
            }
#pragma unroll
            for (int ntp = 0; ntp < 4; ntp++) {
                unsigned t[4];
                ldm_x4(t, bB + (uint32_t)((bRow + ntp * 16) * ROWB + kb + bKh));
                bb[2 * ntp][0] = t[0]; bb[2 * ntp][1] = t[1];
                bb[2 * ntp + 1][0] = t[2]; bb[2 * ntp + 1][1] = t[3];
            }
#pragma unroll
            for (int mt = 0; mt < 4; mt++)
#pragma unroll
                for (int nt = 0; nt < 8; nt++) {
                    mma16816(acc[mt][nt], ah[mt], bb[nt]);
                    mma16816(acc[mt][nt], al[mt], bb[nt]);
                }
        }
    };

    // ---- pipeline: 8 chunks, 2-stage ring ----
    load_chunk(0, 0);
#pragma unroll
    for (int kc = 0; kc < 8; kc++) {
        if (kc < 7) {
            load_chunk(kc + 1, (kc + 1) & 1);
            cp_wait<1>();
        } else {
            cp_wait<0>();
        }
        __syncthreads();
        compute(kc & 1);
        __syncthreads();
    }

    // ---- epilogue: scale, write raw scores, per-row (max,sumexp) partials ----
#pragma unroll
    for (int mt = 0; mt < 4; mt++) {
#pragma unroll
        for (int nt = 0; nt < 8; nt++) {
            int cl = warp_n * 64 + nt * 8 + 2 * q;
            float s0 = sNorm[cl];
            float s1 = sNorm[cl + 1];
            acc[mt][nt][0] *= s0;
            acc[mt][nt][1] *= s1;
            acc[mt][nt][2] *= s0;
            acc[mt][nt][3] *= s1;
        }
#pragma unroll
        for (int h = 0; h < 2; h++) {
            int rloc = warp_m * 64 + mt * 16 + g + h * 8;
            size_t orow = (size_t)(row0 + rloc) * NKEYS + n0;
            float mymax = -3.0e38f;
#pragma unroll
            for (int nt = 0; nt < 8; nt++) {
                int cl = warp_n * 64 + nt * 8 + 2 * q;
                float v0 = acc[mt][nt][h * 2 + 0];
                float v1 = acc[mt][nt][h * 2 + 1];
                *reinterpret_cast<float2*>(out + orow + cl) = make_float2(v0, v1);
                mymax = fmaxf(mymax, fmaxf(v0, v1));
            }
            float s = 0.f;
#pragma unroll
            for (int nt = 0; nt < 8; nt++) {
                s += __expf(acc[mt][nt][h * 2 + 0] - mymax);
                s += __expf(acc[mt][nt][h * 2 + 1] - mymax);
            }
#pragma unroll
            for (int off = 1; off <= 2; off <<= 1) {
                float mo = __shfl_xor_sync(0xffffffffu, mymax, off);
                float so = __shfl_xor_sync(0xffffffffu, s, off);
                float nm = fmaxf(mymax, mo);
                s = s * __expf(mymax - nm) + so * __expf(mo - nm);
                mymax = nm;
            }
            if (q == 0) sRed[warp_n][rloc] = make_float2(mymax, s);
        }
    }
    __syncthreads();
    if (tid < 128) {
        float2 a = sRed[0][tid], b = sRed[1][tid];
        float2 c = sRed[2][tid], d = sRed[3][tid];
        float M = fmaxf(fmaxf(a.x, b.x), fmaxf(c.x, d.x));
        float S = a.y * __expf(a.x - M) + b.y * __expf(b.x - M) +
                  c.y * __expf(c.x - M) + d.y * __expf(d.x - M);
        size_t p = ((size_t)(row0 + tid) * CTILES + blockIdx.y) * 2;
        g_part[p]     = M;
        g_part[p + 1] = S;
    }
}

// ---------------------------------------------------------------
// K3: per-row log-sum-exp reduction of 128 partials
// ---------------------------------------------------------------
__global__ void reduce_kernel() {
    int b = blockIdx.x, t = threadIdx.x;
    size_t base = ((size_t)b * CTILES + t) * 2;
    float m = g_part[base];
    float s = g_part[base + 1];
#pragma unroll
    for (int off = 16; off; off >>= 1) {
        float mo = __shfl_xor_sync(0xffffffffu, m, off);
        float so = __shfl_xor_sync(0xffffffffu, s, off);
        float nm = fmaxf(m, mo);
        s = s * __expf(m - nm) + so * __expf(mo - nm);
        m = nm;
    }
    __shared__ float sm[4], ss[4];
    if ((t & 31) == 0) { sm[t >> 5] = m; ss[t >> 5] = s; }
    __syncthreads();
    if (t < 32) {
        if (t < 4) { m = sm[t]; s = ss[t]; }
        else       { m = -3.0e38f; s = 0.f; }
#pragma unroll
        for (int off = 2; off; off >>= 1) {
            float mo = __shfl_xor_sync(0xffffffffu, m, off);
            float so = __shfl_xor_sync(0xffffffffu, s, off);
            float nm = fmaxf(m, mo);
            s = s * __expf(m - nm) + so * __expf(mo - nm);
            m = nm;
        }
        if (t == 0) g_rowstats[b] = make_float2(m, 1.0f / s);
    }
}

// ---------------------------------------------------------------
// K4: out = exp(score - M) * invS   (in-place over d_out)
// ---------------------------------------------------------------
__global__ void norm_kernel(float* __restrict__ out) {
    const size_t total4 = (size_t)BATCH * NKEYS / 4;
    size_t stride = (size_t)gridDim.x * blockDim.x;
    for (size_t i4 = (size_t)blockIdx.x * blockDim.x + threadIdx.x;
         i4 < total4; i4 += stride) {
        int b = (int)(i4 >> 13);  // 8192 float4 per row
        float2 st = __ldg(&g_rowstats[b]);
        float4 v = reinterpret_cast<float4*>(out)[i4];
        v.x = __expf(v.x - st.x) * st.y;
        v.y = __expf(v.y - st.x) * st.y;
        v.z = __expf(v.z - st.x) * st.y;
        v.w = __expf(v.w - st.x) * st.y;
        reinterpret_cast<float4*>(out)[i4] = v;
    }
}

// ---------------------------------------------------------------
extern "C" void kernel_launch(void* const* d_in, const int* in_sizes, int n_in,
                              void* d_out, int out_size) {
    const float* query  = (const float*)d_in[0];  // [2048, 128]
    const float* keys   = (const float*)d_in[1];  // [32768, 256] (+/-1)
    const float* norms  = (const float*)d_in[2];  // [32768]
    const float* sketch = (const float*)d_in[3];  // [256, 128]
    float* out = (float*)d_out;                   // [2048, 32768]

    cudaFuncSetAttribute(gemm_kernel, cudaFuncAttributeMaxDynamicSharedMemorySize, SMEM_DYN);

    convert_keys<<<(NKEYS * MDIM / 4) / 256, 256>>>(keys);
    project_kernel<<<BATCH, 256>>>(query, sketch);
    dim3 g2(BATCH / 128, CTILES);  // m-fastest: slabs share key tiles in-wave
    gemm_kernel<<<g2, 256, SMEM_DYN>>>(norms, out);
    reduce_kernel<<<BATCH, 128>>>();
    norm_kernel<<<16384, 256>>>(out);
}